// round 1
// baseline (speedup 1.0000x reference)
#include <cuda_runtime.h>

// Problem constants (fixed by the dataset)
#define B_     8
#define L_     8192
#define D_     512
#define NC_    1024
#define SEGLEN 128
#define NSEG   (L_ / SEGLEN)   // 64

// Scratch (allocation-free rule: __device__ globals)
__device__ int2  g_meta[B_ * L_];            // (a' bits, eidx) per (b,t)   512 KB
__device__ float g_C   [B_ * NSEG * D_];     // zero-carry segment results    1 MB
__device__ float g_M   [B_ * NSEG];          // segment decay products
__device__ float g_cin [B_ * NSEG * D_];     // carry-in per segment          1 MB

// ---------------------------------------------------------------------------
// k0: per-batch boundary cumsum -> per-t metadata (a', effective chunk index)
// One block per b, 1024 threads, 8 items/thread, Hillis-Steele block scan.
// ---------------------------------------------------------------------------
__global__ void k0_meta(const float* __restrict__ probs) {
    const int b   = blockIdx.x;
    const int tid = threadIdx.x;
    const int base = tid * 8;

    float4 v0 = *(const float4*)(probs + (size_t)b * L_ + base);
    float4 v1 = *(const float4*)(probs + (size_t)b * L_ + base + 4);
    float p[8] = {v0.x, v0.y, v0.z, v0.w, v1.x, v1.y, v1.z, v1.w};

    int inc[8];
    int run = 0;
#pragma unroll
    for (int i = 0; i < 8; i++) { run += (p[i] > 0.5f) ? 1 : 0; inc[i] = run; }

    __shared__ int sc[1024];
    sc[tid] = run;
    __syncthreads();
    for (int off = 1; off < 1024; off <<= 1) {
        int add = (tid >= off) ? sc[tid - off] : 0;
        __syncthreads();
        sc[tid] += add;
        __syncthreads();
    }
    const int  excl  = sc[tid] - run;
    const bool has_b = sc[1023] > 0;

    int2 o[8];
#pragma unroll
    for (int i = 0; i < 8; i++) {
        int t   = base + i;
        int cnt = excl + inc[i];
        int ei;
        if (has_b) ei = (cnt >= 1 && cnt <= NC_) ? (cnt - 1) : -1;  // clip is a no-op in valid range
        else       ei = t >> 3;                                      // uniform fallback, step = L/NC = 8
        float a = (t == 0) ? 1.0f : p[i];                            // a'[0]=1 encodes s[0]=e[0]
        o[i] = make_int2(__float_as_int(a), ei);
    }
    int4* dst = (int4*)(g_meta + (size_t)b * L_ + base);
#pragma unroll
    for (int i = 0; i < 4; i++)
        dst[i] = make_int4(o[2 * i].x, o[2 * i].y, o[2 * i + 1].x, o[2 * i + 1].y);
}

// ---------------------------------------------------------------------------
// k1: per (b,seg) zero-carry local scan -> C_seg[d], M_seg.
// 256 threads, float2 per thread (D=512). eidx is piecewise constant -> cache e.
// ---------------------------------------------------------------------------
__global__ void k1_partial(const float* __restrict__ x) {
    const int seg = blockIdx.x, b = blockIdx.y;
    const int tid = threadIdx.x;

    __shared__ int2 meta[SEGLEN];
    if (tid < SEGLEN) meta[tid] = g_meta[b * L_ + seg * SEGLEN + tid];
    __syncthreads();

    const float2* xb = (const float2*)(x + (size_t)b * NC_ * D_) + tid;
    float2 s = make_float2(0.f, 0.f);
    float2 e = make_float2(0.f, 0.f);
    float  M = 1.0f;
    int    prev = -2;

#pragma unroll 8
    for (int j = 0; j < SEGLEN; j++) {
        int2  m  = meta[j];
        float a  = __int_as_float(m.x);
        int   ei = m.y;
        if (ei != prev) {                        // uniform branch across block
            e = (ei >= 0) ? __ldg(xb + ei * (D_ / 2)) : make_float2(0.f, 0.f);
            prev = ei;
        }
        float om = 1.0f - a;
        M  *= om;
        s.x = fmaf(a, e.x, om * s.x);
        s.y = fmaf(a, e.y, om * s.y);
    }

    float2* C2 = (float2*)(g_C + ((size_t)b * NSEG + seg) * D_);
    C2[tid] = s;
    if (tid == 0) g_M[b * NSEG + seg] = M;
}

// ---------------------------------------------------------------------------
// k2: per-b affine combine across segments: cin[s] = C[s-1] + M[s-1]*cin[s-1].
// 512 threads (one d each); C column held in registers (fully unrolled).
// ---------------------------------------------------------------------------
__global__ void k2_combine() {
    const int b = blockIdx.x, d = threadIdx.x;

    __shared__ float Ms[NSEG];
    if (d < NSEG) Ms[d] = g_M[b * NSEG + d];
    __syncthreads();

    float Cl[NSEG];
#pragma unroll
    for (int s = 0; s < NSEG; s++)
        Cl[s] = g_C[((size_t)b * NSEG + s) * D_ + d];

    float acc = 0.f;
#pragma unroll
    for (int s = 0; s < NSEG; s++) {
        g_cin[((size_t)b * NSEG + s) * D_ + d] = acc;
        acc = fmaf(Ms[s], acc, Cl[s]);
    }
}

// ---------------------------------------------------------------------------
// k3: re-run each segment with the true carry-in, writing the output.
// ---------------------------------------------------------------------------
__global__ void k3_final(const float* __restrict__ x, float* __restrict__ out) {
    const int seg = blockIdx.x, b = blockIdx.y;
    const int tid = threadIdx.x;

    __shared__ int2 meta[SEGLEN];
    if (tid < SEGLEN) meta[tid] = g_meta[b * L_ + seg * SEGLEN + tid];
    __syncthreads();

    const float2* xb = (const float2*)(x + (size_t)b * NC_ * D_) + tid;
    float2 s = *((const float2*)(g_cin + ((size_t)b * NSEG + seg) * D_) + tid);
    float2 e = make_float2(0.f, 0.f);
    int    prev = -2;

    float2* ob = (float2*)(out + ((size_t)b * L_ + (size_t)seg * SEGLEN) * D_) + tid;

#pragma unroll 8
    for (int j = 0; j < SEGLEN; j++) {
        int2  m  = meta[j];
        float a  = __int_as_float(m.x);
        int   ei = m.y;
        if (ei != prev) {
            e = (ei >= 0) ? __ldg(xb + ei * (D_ / 2)) : make_float2(0.f, 0.f);
            prev = ei;
        }
        float om = 1.0f - a;
        s.x = fmaf(a, e.x, om * s.x);
        s.y = fmaf(a, e.y, om * s.y);
        ob[(size_t)j * (D_ / 2)] = s;
    }
}

// ---------------------------------------------------------------------------
extern "C" void kernel_launch(void* const* d_in, const int* in_sizes, int n_in,
                              void* d_out, int out_size) {
    const float* x     = (const float*)d_in[0];   // compressed_x (B, NC, D)
    const float* probs = (const float*)d_in[1];   // boundary_probs (B, L)
    float*       out   = (float*)d_out;           // (B, L, D)

    k0_meta<<<B_, 1024>>>(probs);
    dim3 grid(NSEG, B_);
    k1_partial<<<grid, D_ / 2>>>(x);
    k2_combine<<<B_, D_>>>();
    k3_final<<<grid, D_ / 2>>>(x, out);
}

// round 2
// speedup vs baseline: 1.0688x; 1.0688x over previous
#include <cuda_runtime.h>

// Problem constants (fixed by the dataset)
#define B_     8
#define L_     8192
#define D_     512
#define NC_    1024
#define SEGLEN 64
#define NSEG   (L_ / SEGLEN)   // 128

// Scratch (allocation-free rule: __device__ globals)
__device__ int2  g_meta[B_ * L_];            // (a' bits, eidx) per (b,t)   512 KB
__device__ float g_C   [B_ * NSEG * D_];     // zero-carry segment results    2 MB
__device__ float g_M   [B_ * NSEG];          // segment decay products
__device__ float g_cin [B_ * NSEG * D_];     // carry-in per segment          2 MB

// ---------------------------------------------------------------------------
// k0: per-batch boundary cumsum -> per-t metadata (a', effective chunk index)
// One block per b, 1024 threads, 8 items/thread, Hillis-Steele block scan.
// ---------------------------------------------------------------------------
__global__ void k0_meta(const float* __restrict__ probs) {
    const int b   = blockIdx.x;
    const int tid = threadIdx.x;
    const int base = tid * 8;

    float4 v0 = *(const float4*)(probs + (size_t)b * L_ + base);
    float4 v1 = *(const float4*)(probs + (size_t)b * L_ + base + 4);
    float p[8] = {v0.x, v0.y, v0.z, v0.w, v1.x, v1.y, v1.z, v1.w};

    int inc[8];
    int run = 0;
#pragma unroll
    for (int i = 0; i < 8; i++) { run += (p[i] > 0.5f) ? 1 : 0; inc[i] = run; }

    __shared__ int sc[1024];
    sc[tid] = run;
    __syncthreads();
    for (int off = 1; off < 1024; off <<= 1) {
        int add = (tid >= off) ? sc[tid - off] : 0;
        __syncthreads();
        sc[tid] += add;
        __syncthreads();
    }
    const int  excl  = sc[tid] - run;
    const bool has_b = sc[1023] > 0;

    int2 o[8];
#pragma unroll
    for (int i = 0; i < 8; i++) {
        int t   = base + i;
        int cnt = excl + inc[i];
        int ei;
        if (has_b) ei = (cnt >= 1 && cnt <= NC_) ? (cnt - 1) : -1;  // clip is no-op in valid range
        else       ei = t >> 3;                                      // uniform fallback, step = 8
        float a = (t == 0) ? 1.0f : p[i];                            // a'[0]=1 encodes s[0]=e[0]
        o[i] = make_int2(__float_as_int(a), ei);
    }
    int4* dst = (int4*)(g_meta + (size_t)b * L_ + base);
#pragma unroll
    for (int i = 0; i < 4; i++)
        dst[i] = make_int4(o[2 * i].x, o[2 * i].y, o[2 * i + 1].x, o[2 * i + 1].y);
}

// ---------------------------------------------------------------------------
// k1: per (b,seg) zero-carry local scan -> C_seg[d], M_seg.
// 128 threads, float4 per thread (D=512). Loads issued unconditionally
// (predicated on ei>=0 only) so unrolling front-batches them off the chain.
// ---------------------------------------------------------------------------
__global__ void k1_partial(const float* __restrict__ x) {
    const int seg = blockIdx.x, b = blockIdx.y;
    const int tid = threadIdx.x;

    __shared__ int2 meta[SEGLEN];
    if (tid < SEGLEN) meta[tid] = g_meta[b * L_ + seg * SEGLEN + tid];
    __syncthreads();

    const float4* xb = (const float4*)(x + (size_t)b * NC_ * D_) + tid;
    float4 s = make_float4(0.f, 0.f, 0.f, 0.f);
    float  M = 1.0f;

#pragma unroll 8
    for (int j = 0; j < SEGLEN; j++) {
        int2  m  = meta[j];
        float a  = __int_as_float(m.x);
        int   ei = m.y;
        float4 e = make_float4(0.f, 0.f, 0.f, 0.f);
        if (ei >= 0) e = __ldg(xb + ei * (D_ / 4));
        float om = 1.0f - a;
        M  *= om;
        s.x = fmaf(a, e.x, om * s.x);
        s.y = fmaf(a, e.y, om * s.y);
        s.z = fmaf(a, e.z, om * s.z);
        s.w = fmaf(a, e.w, om * s.w);
    }

    ((float4*)(g_C + ((size_t)b * NSEG + seg) * D_))[tid] = s;
    if (tid == 0) g_M[b * NSEG + seg] = M;
}

// ---------------------------------------------------------------------------
// k2: per-b affine combine across segments: cin[s] = C[s-1] + M[s-1]*cin[s-1].
// 512 threads (one d each); serial over 128 segments (fma chain only).
// ---------------------------------------------------------------------------
__global__ void k2_combine() {
    const int b = blockIdx.x, d = threadIdx.x;

    __shared__ float Ms[NSEG];
    if (d < NSEG) Ms[d] = g_M[b * NSEG + d];
    __syncthreads();

    float acc = 0.f;
#pragma unroll 8
    for (int s = 0; s < NSEG; s++) {
        g_cin[((size_t)b * NSEG + s) * D_ + d] = acc;
        acc = fmaf(Ms[s], acc, g_C[((size_t)b * NSEG + s) * D_ + d]);
    }
}

// ---------------------------------------------------------------------------
// k3: re-run each segment with the true carry-in, writing the output.
// ---------------------------------------------------------------------------
__global__ void k3_final(const float* __restrict__ x, float* __restrict__ out) {
    const int seg = blockIdx.x, b = blockIdx.y;
    const int tid = threadIdx.x;

    __shared__ int2 meta[SEGLEN];
    if (tid < SEGLEN) meta[tid] = g_meta[b * L_ + seg * SEGLEN + tid];
    __syncthreads();

    const float4* xb = (const float4*)(x + (size_t)b * NC_ * D_) + tid;
    float4 s = ((const float4*)(g_cin + ((size_t)b * NSEG + seg) * D_))[tid];

    float4* ob = (float4*)(out + ((size_t)b * L_ + (size_t)seg * SEGLEN) * D_) + tid;

#pragma unroll 8
    for (int j = 0; j < SEGLEN; j++) {
        int2  m  = meta[j];
        float a  = __int_as_float(m.x);
        int   ei = m.y;
        float4 e = make_float4(0.f, 0.f, 0.f, 0.f);
        if (ei >= 0) e = __ldg(xb + ei * (D_ / 4));
        float om = 1.0f - a;
        s.x = fmaf(a, e.x, om * s.x);
        s.y = fmaf(a, e.y, om * s.y);
        s.z = fmaf(a, e.z, om * s.z);
        s.w = fmaf(a, e.w, om * s.w);
        ob[(size_t)j * (D_ / 4)] = s;
    }
}

// ---------------------------------------------------------------------------
extern "C" void kernel_launch(void* const* d_in, const int* in_sizes, int n_in,
                              void* d_out, int out_size) {
    const float* x     = (const float*)d_in[0];   // compressed_x (B, NC, D)
    const float* probs = (const float*)d_in[1];   // boundary_probs (B, L)
    float*       out   = (float*)d_out;           // (B, L, D)

    k0_meta<<<B_, 1024>>>(probs);
    dim3 grid(NSEG, B_);
    k1_partial<<<grid, D_ / 4>>>(x);
    k2_combine<<<B_, D_>>>();
    k3_final<<<grid, D_ / 4>>>(x, out);
}